// round 12
// baseline (speedup 1.0000x reference)
#include <cuda_runtime.h>
#include <cstdint>

// Problem constants (BATCH=4, SEQ=4096, DIM=1024)
#define B 4
#define L 4096
#define D 1024

// K1 granularity (R4's proven-best read-sweep shape)
#define C1 32
#define NC1 128
#define TPB1 512

// K3 granularity (R9's proven-best write-sweep shape)
#define C3 64
#define NC3 64
#define TPB3 256
#define DBLK3 2
#define G 4

// Scratch (__device__ globals: allocation-free rule)
__device__ float2 g_totals[B * NC1 * D];  // 4 MB: K1 chunk-end states
__device__ float2 g_carry [B * NC3 * D];  // 2 MB: exact state entering each K3 chunk

__device__ __forceinline__ float2 cmul(float2 u, float2 v) {
    return make_float2(fmaf(u.x, v.x, -u.y * v.y), fmaf(u.x, v.y, u.y * v.x));
}

__device__ __forceinline__ float2 decay(float r, float im) {
    float mag = sqrtf(fmaf(r, r, im * im));
    float s = __expf(-mag) / mag;
    return make_float2(r * s, im * s);
}

// ---- K1: zero-init local chunk scans over C1=32 steps. R4 shape. ----
__global__ void __launch_bounds__(TPB1)
k1_totals(const float* __restrict__ x,
          const float* __restrict__ pr, const float* __restrict__ pi,
          const float* __restrict__ ir, const float* __restrict__ ii)
{
    const int d0    = threadIdx.x * 2;
    const int chunk = blockIdx.x;
    const int b     = blockIdx.y;

    const float2 a0 = decay(pr[d0],     pi[d0]);
    const float2 a1 = decay(pr[d0 + 1], pi[d0 + 1]);
    const float2 cre = *(const float2*)(ir + d0);
    const float2 cim = *(const float2*)(ii + d0);

    const float* xp = x + ((size_t)(b * L + chunk * C1)) * D + d0;

    float h0r = 0.f, h0i = 0.f, h1r = 0.f, h1i = 0.f;
#pragma unroll
    for (int t = 0; t < C1; t++) {
        float2 xv = *(const float2*)(xp + (size_t)t * D);
        float n0r = fmaf(a0.x, h0r, fmaf(-a0.y, h0i, cre.x * xv.x));
        float n0i = fmaf(a0.x, h0i, fmaf( a0.y, h0r, cim.x * xv.x));
        float n1r = fmaf(a1.x, h1r, fmaf(-a1.y, h1i, cre.y * xv.y));
        float n1i = fmaf(a1.x, h1i, fmaf( a1.y, h1r, cim.y * xv.y));
        h0r = n0r; h0i = n0i; h1r = n1r; h1i = n1i;
    }
    *(float4*)&g_totals[((size_t)b * NC1 + chunk) * D + d0] =
        make_float4(h0r, h0i, h1r, h1i);
}

// ---- K2: carry chain over 128 totals; emit 64 carries (K3 granularity). ----
// 2048 threads, 2 dims (one float2 chain pair) each.
__global__ void __launch_bounds__(512)
k2_carries(const float* __restrict__ pr, const float* __restrict__ pi,
           const float* __restrict__ lr, const float* __restrict__ li)
{
    const int gid = blockIdx.x * blockDim.x + threadIdx.x;   // 0..2047
    if (gid >= B * D / 2) return;
    const int b  = gid / (D / 2);
    const int d0 = (gid % (D / 2)) * 2;

    float2 aA = decay(pr[d0],     pi[d0]);
    float2 aB = decay(pr[d0 + 1], pi[d0 + 1]);
    // aC1 = a^C1 (C1=32): 5 squarings
#pragma unroll
    for (int k = 0; k < 5; k++) { aA = cmul(aA, aA); aB = cmul(aB, aB); }

    float H0r = lr[b * D + d0],     H0i = li[b * D + d0];
    float H1r = lr[b * D + d0 + 1], H1i = li[b * D + d0 + 1];

#pragma unroll
    for (int base = 0; base < NC1; base += 16) {
        float4 Tb[16];
#pragma unroll
        for (int k = 0; k < 16; k++)
            Tb[k] = __ldg((const float4*)&g_totals[((size_t)b * NC1 + base + k) * D + d0]);
#pragma unroll
        for (int k = 0; k < 16; k++) {
            const int i = base + k;
            if ((i & 1) == 0) {
                *(float4*)&g_carry[((size_t)b * NC3 + (i >> 1)) * D + d0] =
                    make_float4(H0r, H0i, H1r, H1i);
            }
            float n0r = fmaf(aA.x, H0r, fmaf(-aA.y, H0i, Tb[k].x));
            float n0i = fmaf(aA.x, H0i, fmaf( aA.y, H0r, Tb[k].y));
            float n1r = fmaf(aB.x, H1r, fmaf(-aB.y, H1i, Tb[k].z));
            float n1i = fmaf(aB.x, H1i, fmaf( aB.y, H1r, Tb[k].w));
            H0r = n0r; H0i = n0i; H1r = n1r; H1i = n1i;
        }
    }
}

// ---- K3: exact scan over C3=64 seeded with carry; R9 shape; streaming stores. ----
__global__ void __launch_bounds__(TPB3, 4)
k3_scan(const float* __restrict__ x,
        const float* __restrict__ pr, const float* __restrict__ pi,
        const float* __restrict__ ir, const float* __restrict__ ii,
        float* __restrict__ out)
{
    const int d0    = (blockIdx.x * TPB3 + threadIdx.x) * 2;
    const int chunk = blockIdx.y;
    const int b     = blockIdx.z;

    const size_t base = ((size_t)(b * L + chunk * C3)) * D + d0;
    const float* xp = x + base;
    float* op = out + base;

    const float2 a0 = decay(pr[d0],     pi[d0]);
    const float2 a1 = decay(pr[d0 + 1], pi[d0 + 1]);
    const float2 cre = *(const float2*)(ir + d0);
    const float2 cim = *(const float2*)(ii + d0);

    float4 h0 = *(const float4*)&g_carry[((size_t)b * NC3 + chunk) * D + d0];
    float h0r = h0.x, h0i = h0.y, h1r = h0.z, h1i = h0.w;

#pragma unroll
    for (int g = 0; g < C3 / G; g++) {
        float2 xv[G];
#pragma unroll
        for (int k = 0; k < G; k++)
            xv[k] = *(const float2*)(xp + (size_t)(g * G + k) * D);
#pragma unroll
        for (int k = 0; k < G; k++) {
            float n0r = fmaf(a0.x, h0r, fmaf(-a0.y, h0i, cre.x * xv[k].x));
            float n0i = fmaf(a0.x, h0i, fmaf( a0.y, h0r, cim.x * xv[k].x));
            float n1r = fmaf(a1.x, h1r, fmaf(-a1.y, h1i, cre.y * xv[k].y));
            float n1i = fmaf(a1.x, h1i, fmaf( a1.y, h1r, cim.y * xv[k].y));
            h0r = n0r; h0i = n0i; h1r = n1r; h1i = n1i;
            __stcs((float2*)(op + (size_t)(g * G + k) * D), make_float2(h0r, h1r));
        }
    }
}

extern "C" void kernel_launch(void* const* d_in, const int* in_sizes, int n_in,
                              void* d_out, int out_size) {
    const float* x    = (const float*)d_in[0];
    const float* p_re = (const float*)d_in[1];
    const float* p_im = (const float*)d_in[2];
    const float* i_re = (const float*)d_in[3];
    const float* i_im = (const float*)d_in[4];
    const float* lc_r = (const float*)d_in[5];
    const float* lc_i = (const float*)d_in[6];
    float* out = (float*)d_out;

    dim3 grid1(NC1, B);          // 512 blocks x 512 threads
    k1_totals<<<grid1, TPB1>>>(x, p_re, p_im, i_re, i_im);

    k2_carries<<<4, 512>>>(p_re, p_im, lc_r, lc_i);

    dim3 grid3(DBLK3, NC3, B);   // (2, 64, 4) = 512 blocks x 256 threads
    k3_scan<<<grid3, TPB3>>>(x, p_re, p_im, i_re, i_im, out);
}